// round 3
// baseline (speedup 1.0000x reference)
#include <cuda_runtime.h>

// ---------------------------------------------------------------------------
// GraphPooling: 3-layer GAT (single head) + final projection, fp32.
// ---------------------------------------------------------------------------

#define NMAX 50000
#define FMAX 128

__device__ float g_hbuf  [NMAX * FMAX];
__device__ float g_accbuf[NMAX * FMAX];
__device__ float g_actbuf[NMAX * FMAX];
__device__ float g_as [NMAX];
__device__ float g_ad [NMAX];
__device__ float g_m  [NMAX];
__device__ float g_den[NMAX];
__device__ float g_ST [64 * 512];

__device__ __forceinline__ float leaky02(float v) { return v > 0.f ? v : 0.2f * v; }

__device__ __forceinline__ void atomicMaxFloat(float* addr, float val) {
    if (val >= 0.f) atomicMax((int*)addr, __float_as_int(val));
    else            atomicMin((unsigned int*)addr, __float_as_uint(val));
}

// ---------------------------------------------------------------------------
// Register-tiled SGEMM: C[M,N] = A[M,K] @ B[K,N]  (B row-major)
// ---------------------------------------------------------------------------
template<int BM, int BN, int BK, int TM, int TN>
__global__ void __launch_bounds__((BM/TM)*(BN/TN))
sgemm_kernel(const float* __restrict__ A, const float* __restrict__ B,
             float* __restrict__ C, int M, int N, int K)
{
    constexpr int THREADS = (BM/TM) * (BN/TN);
    __shared__ float As[BK][BM];
    __shared__ float Bs[BK][BN];

    const int tid  = threadIdx.x;
    const int m0   = blockIdx.x * BM;
    const int n0   = blockIdx.y * BN;
    const int tcol = tid % (BN / TN);
    const int trow = tid / (BN / TN);

    float acc[TM][TN];
#pragma unroll
    for (int i = 0; i < TM; i++)
#pragma unroll
        for (int j = 0; j < TN; j++) acc[i][j] = 0.f;

    constexpr int A_F4  = BM * BK / 4;
    constexpr int A_PER = A_F4 / THREADS;
    constexpr int B_F4  = BK * BN / 4;
    constexpr int B_PER = B_F4 / THREADS;

    for (int k0 = 0; k0 < K; k0 += BK) {
#pragma unroll
        for (int i = 0; i < A_PER; i++) {
            int idx = tid + i * THREADS;
            int row = idx / (BK / 4);
            int kq  = idx % (BK / 4);
            int gr  = m0 + row;
            float4 v = make_float4(0.f, 0.f, 0.f, 0.f);
            if (gr < M) v = *(const float4*)(A + (size_t)gr * K + k0 + kq * 4);
            As[kq*4+0][row] = v.x;
            As[kq*4+1][row] = v.y;
            As[kq*4+2][row] = v.z;
            As[kq*4+3][row] = v.w;
        }
#pragma unroll
        for (int i = 0; i < B_PER; i++) {
            int idx = tid + i * THREADS;
            int row = idx / (BN / 4);
            int c4  = idx % (BN / 4);
            float4 v = *(const float4*)(B + (size_t)(k0 + row) * N + n0 + c4 * 4);
            *(float4*)&Bs[row][c4 * 4] = v;
        }
        __syncthreads();

#pragma unroll
        for (int kk = 0; kk < BK; kk++) {
            float4 a0 = *(const float4*)&As[kk][trow * TM];
            float4 a1 = *(const float4*)&As[kk][trow * TM + 4];
            float4 b0 = *(const float4*)&Bs[kk][tcol * TN];
            float ar[TM] = {a0.x, a0.y, a0.z, a0.w, a1.x, a1.y, a1.z, a1.w};
            float br[TN] = {b0.x, b0.y, b0.z, b0.w};
#pragma unroll
            for (int i = 0; i < TM; i++)
#pragma unroll
                for (int j = 0; j < TN; j++)
                    acc[i][j] = fmaf(ar[i], br[j], acc[i][j]);
        }
        __syncthreads();
    }

#pragma unroll
    for (int i = 0; i < TM; i++) {
        int gr = m0 + trow * TM + i;
        if (gr < M) {
            float4 v = make_float4(acc[i][0], acc[i][1], acc[i][2], acc[i][3]);
            *(float4*)(C + (size_t)gr * N + n0 + tcol * TN) = v;
        }
    }
}

// ---------------------------------------------------------------------------
// Per-node attention scalars; one warp per node.
// ---------------------------------------------------------------------------
template<int F>
__global__ void alpha_kernel(const float* __restrict__ h,
                             const float* __restrict__ avs,
                             const float* __restrict__ avd,
                             float* __restrict__ oas, float* __restrict__ oad,
                             float* __restrict__ om, int N)
{
    int warp = (blockIdx.x * blockDim.x + threadIdx.x) >> 5;
    int lane = threadIdx.x & 31;
    if (warp >= N) return;
    const float* row = h + (size_t)warp * F;
    float s = 0.f, d = 0.f;
#pragma unroll
    for (int q = 0; q < F / 32; q++) {
        float hv = row[lane + 32 * q];
        s = fmaf(hv, avs[lane + 32 * q], s);
        d = fmaf(hv, avd[lane + 32 * q], d);
    }
#pragma unroll
    for (int o = 16; o; o >>= 1) {
        s += __shfl_xor_sync(0xffffffffu, s, o);
        d += __shfl_xor_sync(0xffffffffu, d, o);
    }
    if (lane == 0) {
        oas[warp] = s;
        oad[warp] = d;
        om[warp]  = leaky02(s + d);   // self-loop seeds the segment max
    }
}

// segment max over real edges (edge_index is int32: src at [0,E), dst at [E,2E))
__global__ void edge_max_kernel(const int* __restrict__ ei,
                                const float* __restrict__ as_,
                                const float* __restrict__ ad_,
                                float* __restrict__ m, int E)
{
    for (int e = blockIdx.x * blockDim.x + threadIdx.x; e < E;
         e += gridDim.x * blockDim.x) {
        int s = ei[e];
        int d = ei[E + e];
        float v = leaky02(as_[s] + ad_[d]);
        atomicMaxFloat(&m[d], v);
    }
}

__global__ void den_init_kernel(const float* __restrict__ as_,
                                const float* __restrict__ ad_,
                                const float* __restrict__ m,
                                float* __restrict__ den, int N)
{
    int i = blockIdx.x * blockDim.x + threadIdx.x;
    if (i < N) {
        float v = leaky02(as_[i] + ad_[i]);
        den[i] = expf(v - m[i]);
    }
}

__global__ void scale_init_kernel(const float* __restrict__ h,
                                  const float* __restrict__ den,
                                  float* __restrict__ out, int total, int shift)
{
    for (int i = blockIdx.x * blockDim.x + threadIdx.x; i < total;
         i += gridDim.x * blockDim.x) {
        out[i] = den[i >> shift] * h[i];
    }
}

// edge aggregation: F/4 lanes per edge, float4 vector atomics
template<int F>
__global__ void edge_agg_kernel(const int* __restrict__ ei,
                                const float* __restrict__ as_,
                                const float* __restrict__ ad_,
                                const float* __restrict__ m,
                                float* __restrict__ den,
                                const float* __restrict__ h,
                                float* __restrict__ out, int E)
{
    constexpr int LPE = F / 4;
    constexpr int EPW = 32 / LPE;
    int lane = threadIdx.x & 31;
    int sub  = lane / LPE;
    int l    = lane % LPE;
    int gw   = (blockIdx.x * blockDim.x + threadIdx.x) >> 5;
    int e    = gw * EPW + sub;
    if (e >= E) return;

    int s = ei[e];
    int d = ei[E + e];
    float v = leaky02(as_[s] + ad_[d]);
    float w = expf(v - m[d]);
    if (l == 0) atomicAdd(&den[d], w);

    float4 hv = *(const float4*)(h + (size_t)s * F + l * 4);
    float4* dst = (float4*)(out + (size_t)d * F + l * 4);
    atomicAdd(dst, make_float4(w * hv.x, w * hv.y, w * hv.z, w * hv.w));
}

__global__ void finalize_kernel(const float* __restrict__ acc,
                                const float* __restrict__ den,
                                const float* __restrict__ bias,
                                float* __restrict__ dst,
                                int total, int shift, int mask, int do_leaky)
{
    for (int i = blockIdx.x * blockDim.x + threadIdx.x; i < total;
         i += gridDim.x * blockDim.x) {
        float v = acc[i] / den[i >> shift] + bias[i & mask];
        if (do_leaky) v = v > 0.f ? v : 0.1f * v;
        dst[i] = v;
    }
}

__global__ void transpose_S_kernel(const float* __restrict__ S, float* __restrict__ ST)
{
    int i = blockIdx.x * blockDim.x + threadIdx.x;
    if (i < 64 * 512) {
        int k = i / 512, n = i % 512;
        ST[i] = S[n * 64 + k];
    }
}

// ---------------------------------------------------------------------------
// Host
// ---------------------------------------------------------------------------
static inline int cdiv(int a, int b) { return (a + b - 1) / b; }

static void gat_layer(const float* Ain, int K, int F,
                      const float* W, const float* avs, const float* avd,
                      const float* bias, bool do_leaky,
                      int N, int E, const int* ei,
                      float* hb, float* ab, float* outb,
                      float* pas, float* pad_, float* pm, float* pden)
{
    if (F == 128)
        sgemm_kernel<64,128,16,8,4><<<dim3(cdiv(N,64),1), 256>>>(Ain, W, hb, N, F, K);
    else
        sgemm_kernel<64,64,16,8,4><<<dim3(cdiv(N,64),1), 128>>>(Ain, W, hb, N, F, K);

    if (F == 128) alpha_kernel<128><<<cdiv(N,8), 256>>>(hb, avs, avd, pas, pad_, pm, N);
    else          alpha_kernel<64> <<<cdiv(N,8), 256>>>(hb, avs, avd, pas, pad_, pm, N);

    edge_max_kernel<<<cdiv(E,256), 256>>>(ei, pas, pad_, pm, E);
    den_init_kernel<<<cdiv(N,256), 256>>>(pas, pad_, pm, pden, N);

    int total = N * F;
    int shift = (F == 128) ? 7 : 6;
    scale_init_kernel<<<cdiv(total,256), 256>>>(hb, pden, ab, total, shift);

    if (F == 128)
        edge_agg_kernel<128><<<cdiv(E*32,256), 256>>>(ei, pas, pad_, pm, pden, hb, ab, E);
    else
        edge_agg_kernel<64> <<<cdiv(E*16,256), 256>>>(ei, pas, pad_, pm, pden, hb, ab, E);

    finalize_kernel<<<cdiv(total,256), 256>>>(ab, pden, bias, outb, total, shift,
                                              F - 1, do_leaky ? 1 : 0);
}

extern "C" void kernel_launch(void* const* d_in, const int* in_sizes, int n_in,
                              void* d_out, int out_size)
{
    const float* x   = (const float*)d_in[0];
    const int*   ei  = (const int*)d_in[1];   // int32: JAX x64 disabled downcasts int64
    const float* W1  = (const float*)d_in[2];
    const float* a1s = (const float*)d_in[3];
    const float* a1d = (const float*)d_in[4];
    const float* b1  = (const float*)d_in[5];
    const float* W2  = (const float*)d_in[6];
    const float* a2s = (const float*)d_in[7];
    const float* a2d = (const float*)d_in[8];
    const float* b2  = (const float*)d_in[9];
    const float* W3  = (const float*)d_in[10];
    const float* a3s = (const float*)d_in[11];
    const float* a3d = (const float*)d_in[12];
    const float* b3  = (const float*)d_in[13];
    const float* S   = (const float*)d_in[14];

    int N = in_sizes[0] / 128;
    int E = in_sizes[1] / 2;

    float *hb, *ab, *actb, *pas, *pad_, *pm, *pden, *pst;
    cudaGetSymbolAddress((void**)&hb,   g_hbuf);
    cudaGetSymbolAddress((void**)&ab,   g_accbuf);
    cudaGetSymbolAddress((void**)&actb, g_actbuf);
    cudaGetSymbolAddress((void**)&pas,  g_as);
    cudaGetSymbolAddress((void**)&pad_, g_ad);
    cudaGetSymbolAddress((void**)&pm,   g_m);
    cudaGetSymbolAddress((void**)&pden, g_den);
    cudaGetSymbolAddress((void**)&pst,  g_ST);

    transpose_S_kernel<<<cdiv(64*512,256), 256>>>(S, pst);

    gat_layer(x,    128, 128, W1, a1s, a1d, b1, true,  N, E, ei, hb, ab, actb, pas, pad_, pm, pden);
    gat_layer(actb, 128, 128, W2, a2s, a2d, b2, true,  N, E, ei, hb, ab, actb, pas, pad_, pm, pden);
    gat_layer(actb, 128, 64,  W3, a3s, a3d, b3, false, N, E, ei, hb, ab, actb, pas, pad_, pm, pden);

    sgemm_kernel<64,128,16,8,4><<<dim3(cdiv(N,64), 4), 256>>>(actb, pst, (float*)d_out, N, 512, 64);
}

// round 4
// speedup vs baseline: 1.2579x; 1.2579x over previous
#include <cuda_runtime.h>

// ---------------------------------------------------------------------------
// GraphPooling: 3-layer GAT (single head) + final projection, fp32.
// Round 4: CSR-based gather aggregation (no atomics in hot loops) +
//          128x128 register-tiled SGEMM.
// ---------------------------------------------------------------------------

#define NMAX 50000
#define EMAX 800000
#define FMAX 128

__device__ float g_hbuf  [NMAX * FMAX];   // h of current layer (GEMM out)
__device__ float g_actbuf[NMAX * FMAX];   // activated output = next layer input
__device__ float g_as   [NMAX];
__device__ float g_ad   [NMAX];
__device__ float g_den  [NMAX];
__device__ float g_wself[NMAX];
__device__ float g_ew   [EMAX];           // per-edge scores -> weights (CSR order)
__device__ int   g_csrc [EMAX];           // src node per CSR slot
__device__ int   g_rp   [NMAX + 1];       // CSR row pointers (by dst)
__device__ int   g_cur  [NMAX];           // scatter cursors
__device__ int   g_cnt  [NMAX];           // in-degree histogram
__device__ float g_ST   [64 * 512];       // S transposed

__device__ __forceinline__ float leaky02(float v) { return v > 0.f ? v : 0.2f * v; }

// ---------------------------------------------------------------------------
// SGEMM: C[M,Ncols] = A[M,K] @ B[K,Ncols], 128-wide register tiling
// ---------------------------------------------------------------------------
template<int BM, int BN, int BK, int TM, int TN>
__global__ void __launch_bounds__((BM/TM)*(BN/TN))
sgemm_kernel(const float* __restrict__ A, const float* __restrict__ B,
             float* __restrict__ C, int M, int Ncols, int K)
{
    constexpr int THREADS = (BM/TM) * (BN/TN);
    __shared__ float As[BK][BM];
    __shared__ float Bs[BK][BN];

    const int tid  = threadIdx.x;
    const int m0   = blockIdx.x * BM;
    const int n0   = blockIdx.y * BN;
    const int tcol = tid % (BN / TN);
    const int trow = tid / (BN / TN);

    float acc[TM][TN];
#pragma unroll
    for (int i = 0; i < TM; i++)
#pragma unroll
        for (int j = 0; j < TN; j++) acc[i][j] = 0.f;

    constexpr int A_PER = (BM * BK / 4) / THREADS;
    constexpr int B_PER = (BK * BN / 4) / THREADS;

    for (int k0 = 0; k0 < K; k0 += BK) {
#pragma unroll
        for (int i = 0; i < A_PER; i++) {
            int idx = tid + i * THREADS;
            int row = idx / (BK / 4);
            int kq  = idx % (BK / 4);
            int gr  = m0 + row;
            float4 v = make_float4(0.f, 0.f, 0.f, 0.f);
            if (gr < M) v = *(const float4*)(A + (size_t)gr * K + k0 + kq * 4);
            As[kq*4+0][row] = v.x;
            As[kq*4+1][row] = v.y;
            As[kq*4+2][row] = v.z;
            As[kq*4+3][row] = v.w;
        }
#pragma unroll
        for (int i = 0; i < B_PER; i++) {
            int idx = tid + i * THREADS;
            int row = idx / (BN / 4);
            int c4  = idx % (BN / 4);
            float4 v = *(const float4*)(B + (size_t)(k0 + row) * Ncols + n0 + c4 * 4);
            *(float4*)&Bs[row][c4 * 4] = v;
        }
        __syncthreads();

#pragma unroll
        for (int kk = 0; kk < BK; kk++) {
            float ar[TM], br[TN];
#pragma unroll
            for (int q = 0; q < TM / 4; q++) {
                float4 a = *(const float4*)&As[kk][trow * TM + q * 4];
                ar[q*4+0] = a.x; ar[q*4+1] = a.y; ar[q*4+2] = a.z; ar[q*4+3] = a.w;
            }
#pragma unroll
            for (int q = 0; q < TN / 4; q++) {
                float4 b = *(const float4*)&Bs[kk][tcol * TN + q * 4];
                br[q*4+0] = b.x; br[q*4+1] = b.y; br[q*4+2] = b.z; br[q*4+3] = b.w;
            }
#pragma unroll
            for (int i = 0; i < TM; i++)
#pragma unroll
                for (int j = 0; j < TN; j++)
                    acc[i][j] = fmaf(ar[i], br[j], acc[i][j]);
        }
        __syncthreads();
    }

#pragma unroll
    for (int i = 0; i < TM; i++) {
        int gr = m0 + trow * TM + i;
        if (gr < M) {
#pragma unroll
            for (int q = 0; q < TN / 4; q++) {
                float4 v = make_float4(acc[i][q*4+0], acc[i][q*4+1],
                                       acc[i][q*4+2], acc[i][q*4+3]);
                *(float4*)(C + (size_t)gr * Ncols + n0 + tcol * TN + q * 4) = v;
            }
        }
    }
}

// ---------------------------------------------------------------------------
// CSR build
// ---------------------------------------------------------------------------
__global__ void zero_cnt_kernel(int* __restrict__ cnt, int N)
{
    int i = blockIdx.x * blockDim.x + threadIdx.x;
    if (i < N) cnt[i] = 0;
}

__global__ void hist_kernel(const int* __restrict__ ei, int* __restrict__ cnt, int E)
{
    int e = blockIdx.x * blockDim.x + threadIdx.x;
    if (e < E) atomicAdd(&cnt[ei[E + e]], 1);
}

// single-block exclusive scan: rowptr[i] = sum cnt[0..i-1], rowptr[N] = E
__global__ void __launch_bounds__(1024)
scan_kernel(const int* __restrict__ cnt, int* __restrict__ rp,
            int* __restrict__ cur, int N)
{
    __shared__ int sh[1024];
    int t = threadIdx.x;
    int IT = (N + 1023) / 1024;
    int base = t * IT;

    int sum = 0;
    for (int k = 0; k < IT; k++) {
        int idx = base + k;
        if (idx < N) sum += cnt[idx];
    }
    sh[t] = sum;
    __syncthreads();
    for (int off = 1; off < 1024; off <<= 1) {
        int v = (t >= off) ? sh[t - off] : 0;
        __syncthreads();
        sh[t] += v;
        __syncthreads();
    }
    int run = sh[t] - sum;   // exclusive prefix of this chunk
    for (int k = 0; k < IT; k++) {
        int idx = base + k;
        if (idx < N) {
            rp[idx]  = run;
            cur[idx] = run;
            run += cnt[idx];
        }
    }
    if (t == 1023) rp[N] = sh[1023];
}

__global__ void scatter_kernel(const int* __restrict__ ei, int* __restrict__ cur,
                               int* __restrict__ csrc, int E)
{
    int e = blockIdx.x * blockDim.x + threadIdx.x;
    if (e < E) {
        int d = ei[E + e];
        int pos = atomicAdd(&cur[d], 1);
        csrc[pos] = ei[e];
    }
}

// ---------------------------------------------------------------------------
// Per-node attention scalars; one warp per node.
// ---------------------------------------------------------------------------
template<int F>
__global__ void alpha_kernel(const float* __restrict__ h,
                             const float* __restrict__ avs,
                             const float* __restrict__ avd,
                             float* __restrict__ oas, float* __restrict__ oad, int N)
{
    int warp = (blockIdx.x * blockDim.x + threadIdx.x) >> 5;
    int lane = threadIdx.x & 31;
    if (warp >= N) return;
    const float* row = h + (size_t)warp * F;
    float s = 0.f, d = 0.f;
#pragma unroll
    for (int q = 0; q < F / 32; q++) {
        float hv = row[lane + 32 * q];
        s = fmaf(hv, avs[lane + 32 * q], s);
        d = fmaf(hv, avd[lane + 32 * q], d);
    }
#pragma unroll
    for (int o = 16; o; o >>= 1) {
        s += __shfl_xor_sync(0xffffffffu, s, o);
        d += __shfl_xor_sync(0xffffffffu, d, o);
    }
    if (lane == 0) {
        oas[warp] = s;
        oad[warp] = d;
    }
}

// ---------------------------------------------------------------------------
// Per-node softmax over incoming edges (CSR). One warp per node.
// Pass A: score -> ew[], track max. Pass B: exp -> ew[], sum -> den.
// ---------------------------------------------------------------------------
__global__ void node_attn_kernel(const int* __restrict__ rp,
                                 const int* __restrict__ csrc,
                                 const float* __restrict__ as_,
                                 const float* __restrict__ ad_,
                                 float* __restrict__ ew,
                                 float* __restrict__ den,
                                 float* __restrict__ wself, int N)
{
    int node = (blockIdx.x * blockDim.x + threadIdx.x) >> 5;
    int lane = threadIdx.x & 31;
    if (node >= N) return;

    int j0 = rp[node], j1 = rp[node + 1];
    float add   = ad_[node];
    float vself = leaky02(as_[node] + add);
    float mx = vself;

    for (int j = j0 + lane; j < j1; j += 32) {
        float v = leaky02(as_[csrc[j]] + add);
        ew[j] = v;
        mx = fmaxf(mx, v);
    }
#pragma unroll
    for (int o = 16; o; o >>= 1)
        mx = fmaxf(mx, __shfl_xor_sync(0xffffffffu, mx, o));

    float sum = 0.f;
    for (int j = j0 + lane; j < j1; j += 32) {
        float w = expf(ew[j] - mx);
        ew[j] = w;
        sum += w;
    }
#pragma unroll
    for (int o = 16; o; o >>= 1)
        sum += __shfl_xor_sync(0xffffffffu, sum, o);

    if (lane == 0) {
        float ws = expf(vself - mx);
        den[node]   = sum + ws;
        wself[node] = ws;
    }
}

// ---------------------------------------------------------------------------
// CSR aggregation, fused with self-loop, normalization, bias, activation.
// F=128: warp per node (32 lanes x float4). F=64: half-warp per node.
// ---------------------------------------------------------------------------
template<int F>
__global__ void agg_csr_kernel(const int* __restrict__ rp,
                               const int* __restrict__ csrc,
                               const float* __restrict__ ew,
                               const float* __restrict__ den,
                               const float* __restrict__ wself,
                               const float* __restrict__ h,
                               const float* __restrict__ bias,
                               float* __restrict__ out, int N, int do_leaky)
{
    constexpr int LPN = F / 4;      // lanes per node
    constexpr int NPW = 32 / LPN;   // nodes per warp
    int lane = threadIdx.x & 31;
    int sub  = lane / LPN;
    int l    = lane % LPN;
    int node = ((blockIdx.x * blockDim.x + threadIdx.x) >> 5) * NPW + sub;
    if (node >= N) return;

    float ws = wself[node];
    float4 hv = *(const float4*)(h + (size_t)node * F + l * 4);
    float ax = ws * hv.x, ay = ws * hv.y, az = ws * hv.z, aw = ws * hv.w;

    int j0 = rp[node], j1 = rp[node + 1];
    for (int j = j0; j < j1; j++) {
        int   s = __ldg(&csrc[j]);
        float w = __ldg(&ew[j]);
        float4 v = *(const float4*)(h + (size_t)s * F + l * 4);
        ax = fmaf(w, v.x, ax);
        ay = fmaf(w, v.y, ay);
        az = fmaf(w, v.z, az);
        aw = fmaf(w, v.w, aw);
    }

    float inv = 1.f / den[node];
    float4 b = *(const float4*)(bias + l * 4);
    float4 o;
    o.x = ax * inv + b.x;
    o.y = ay * inv + b.y;
    o.z = az * inv + b.z;
    o.w = aw * inv + b.w;
    if (do_leaky) {
        o.x = o.x > 0.f ? o.x : 0.1f * o.x;
        o.y = o.y > 0.f ? o.y : 0.1f * o.y;
        o.z = o.z > 0.f ? o.z : 0.1f * o.z;
        o.w = o.w > 0.f ? o.w : 0.1f * o.w;
    }
    *(float4*)(out + (size_t)node * F + l * 4) = o;
}

__global__ void transpose_S_kernel(const float* __restrict__ S, float* __restrict__ ST)
{
    int i = blockIdx.x * blockDim.x + threadIdx.x;
    if (i < 64 * 512) {
        int k = i / 512, n = i % 512;
        ST[i] = S[n * 64 + k];
    }
}

// ---------------------------------------------------------------------------
// Host
// ---------------------------------------------------------------------------
static inline int cdiv(int a, int b) { return (a + b - 1) / b; }

struct Bufs {
    float *hb, *actb, *pas, *pad_, *pden, *pws, *pew, *pst;
    int *pcsrc, *prp, *pcur, *pcnt;
};

static void gat_layer(const float* Ain, int K, int F,
                      const float* W, const float* avs, const float* avd,
                      const float* bias, bool do_leaky,
                      int N, const Bufs& b)
{
    if (F == 128)
        sgemm_kernel<128,128,16,8,8><<<dim3(cdiv(N,128),1), 256>>>(Ain, W, b.hb, N, F, K);
    else
        sgemm_kernel<128,64,16,8,8><<<dim3(cdiv(N,128),1), 128>>>(Ain, W, b.hb, N, F, K);

    if (F == 128) alpha_kernel<128><<<cdiv(N*32,256), 256>>>(b.hb, avs, avd, b.pas, b.pad_, N);
    else          alpha_kernel<64> <<<cdiv(N*32,256), 256>>>(b.hb, avs, avd, b.pas, b.pad_, N);

    node_attn_kernel<<<cdiv(N*32,256), 256>>>(b.prp, b.pcsrc, b.pas, b.pad_,
                                              b.pew, b.pden, b.pws, N);

    if (F == 128)
        agg_csr_kernel<128><<<cdiv(N*32,256), 256>>>(b.prp, b.pcsrc, b.pew, b.pden,
                                                     b.pws, b.hb, bias, b.actb, N,
                                                     do_leaky ? 1 : 0);
    else
        agg_csr_kernel<64><<<cdiv(N*16,256), 256>>>(b.prp, b.pcsrc, b.pew, b.pden,
                                                    b.pws, b.hb, bias, b.actb, N,
                                                    do_leaky ? 1 : 0);
}

extern "C" void kernel_launch(void* const* d_in, const int* in_sizes, int n_in,
                              void* d_out, int out_size)
{
    const float* x   = (const float*)d_in[0];
    const int*   ei  = (const int*)d_in[1];   // int32 (JAX x64 disabled)
    const float* W1  = (const float*)d_in[2];
    const float* a1s = (const float*)d_in[3];
    const float* a1d = (const float*)d_in[4];
    const float* b1  = (const float*)d_in[5];
    const float* W2  = (const float*)d_in[6];
    const float* a2s = (const float*)d_in[7];
    const float* a2d = (const float*)d_in[8];
    const float* b2  = (const float*)d_in[9];
    const float* W3  = (const float*)d_in[10];
    const float* a3s = (const float*)d_in[11];
    const float* a3d = (const float*)d_in[12];
    const float* b3  = (const float*)d_in[13];
    const float* S   = (const float*)d_in[14];

    int N = in_sizes[0] / 128;
    int E = in_sizes[1] / 2;

    Bufs b;
    cudaGetSymbolAddress((void**)&b.hb,    g_hbuf);
    cudaGetSymbolAddress((void**)&b.actb,  g_actbuf);
    cudaGetSymbolAddress((void**)&b.pas,   g_as);
    cudaGetSymbolAddress((void**)&b.pad_,  g_ad);
    cudaGetSymbolAddress((void**)&b.pden,  g_den);
    cudaGetSymbolAddress((void**)&b.pws,   g_wself);
    cudaGetSymbolAddress((void**)&b.pew,   g_ew);
    cudaGetSymbolAddress((void**)&b.pst,   g_ST);
    cudaGetSymbolAddress((void**)&b.pcsrc, g_csrc);
    cudaGetSymbolAddress((void**)&b.prp,   g_rp);
    cudaGetSymbolAddress((void**)&b.pcur,  g_cur);
    cudaGetSymbolAddress((void**)&b.pcnt,  g_cnt);

    // --- CSR build (per launch, graph-capturable) ---
    zero_cnt_kernel<<<cdiv(N,256), 256>>>(b.pcnt, N);
    hist_kernel<<<cdiv(E,256), 256>>>(ei, b.pcnt, E);
    scan_kernel<<<1, 1024>>>(b.pcnt, b.prp, b.pcur, N);
    scatter_kernel<<<cdiv(E,256), 256>>>(ei, b.pcur, b.pcsrc, E);

    transpose_S_kernel<<<cdiv(64*512,256), 256>>>(S, b.pst);

    // --- layers ---
    gat_layer(x,      128, 128, W1, a1s, a1d, b1, true,  N, b);
    gat_layer(b.actb, 128, 128, W2, a2s, a2d, b2, true,  N, b);
    gat_layer(b.actb, 128, 64,  W3, a3s, a3d, b3, false, N, b);

    // --- final projection: [N,64] @ [64,512] ---
    sgemm_kernel<128,128,16,8,8><<<dim3(cdiv(N,128), 4), 256>>>(b.actb, b.pst,
                                                                (float*)d_out, N, 512, 64);
}